// round 17
// baseline (speedup 1.0000x reference)
#include <cuda_runtime.h>
#include <cuda_bf16.h>
#include <cstdint>

// Problem dims
#define B_ 32
#define S_ 64
#define T_ 64
#define E_ 128
#define H_ 256
#define V_ 32000
#define FOURH 1024
#define MPAD 2048   // padded row count (2016 real decoder rows)

// LSTM cluster config (proven 324us design)
#define CSIZE 8
#define LSTM_CTAS 128
#define STEP_TX_BYTES 2048u

// -------- device scratch (allocation-free: __device__ globals) --------
__device__ __align__(16) float g_Xenc[MPAD * FOURH];
__device__ __align__(16) float g_Xdec[MPAD * FOURH];
__device__ __align__(16) __nv_bfloat16 g_Ahi[MPAD * H_];   // decoder hs split-hi, row m=t*32+b
__device__ __align__(16) __nv_bfloat16 g_Alo[MPAD * H_];   // decoder hs split-lo
__device__ __align__(16) __nv_bfloat16 g_Bhi[V_ * H_];     // fc_W split-hi
__device__ __align__(16) __nv_bfloat16 g_Blo[V_ * H_];     // fc_W split-lo

// -------- packed f32x2 helpers --------
static __device__ __forceinline__ unsigned long long ffma2(unsigned long long a,
                                                           unsigned long long b,
                                                           unsigned long long c) {
    unsigned long long d;
    asm("fma.rn.f32x2 %0, %1, %2, %3;" : "=l"(d) : "l"(a), "l"(b), "l"(c));
    return d;
}
static __device__ __forceinline__ unsigned long long dup2(float a) {
    unsigned long long r;
    asm("mov.b64 %0, {%1, %1};" : "=l"(r) : "f"(a));
    return r;
}
static __device__ __forceinline__ float2 unpk(unsigned long long v) {
    float lo, hi;
    asm("mov.b64 {%0, %1}, %2;" : "=f"(lo), "=f"(hi) : "l"(v));
    return make_float2(lo, hi);
}

// -------- fast activations (MUFU-only) --------
static __device__ __forceinline__ float fsigmoid(float x) {
    return __fdividef(1.f, 1.f + __expf(-x));
}
static __device__ __forceinline__ float ftanh(float x) {
    return 1.f - __fdividef(2.f, __expf(2.f * x) + 1.f);
}

// -------- cluster / mbarrier helpers --------
static __device__ __forceinline__ uint32_t ctarank() {
    uint32_t r; asm("mov.u32 %0, %%cluster_ctarank;" : "=r"(r)); return r;
}
static __device__ __forceinline__ uint32_t smem_u32(const void* p) {
    uint32_t a;
    asm("{ .reg .u64 t; cvta.to.shared.u64 t, %1; cvt.u32.u64 %0, t; }"
        : "=r"(a) : "l"(p));
    return a;
}
static __device__ __forceinline__ void cluster_sync() {
    asm volatile("barrier.cluster.arrive.aligned;" ::: "memory");
    asm volatile("barrier.cluster.wait.aligned;" ::: "memory");
}
static __device__ __forceinline__ void mbar_init(uint32_t mbar, uint32_t cnt) {
    asm volatile("mbarrier.init.shared.b64 [%0], %1;" :: "r"(mbar), "r"(cnt) : "memory");
}
static __device__ __forceinline__ void mbar_expect_tx(uint32_t mbar, uint32_t bytes) {
    asm volatile("mbarrier.arrive.expect_tx.shared.b64 _, [%0], %1;"
                 :: "r"(mbar), "r"(bytes) : "memory");
}
static __device__ __forceinline__ void mbar_wait_parity(uint32_t mbar, uint32_t parity) {
    uint32_t done;
    asm volatile(
        "{\n\t.reg .pred p;\n\t"
        "mbarrier.try_wait.parity.acquire.cta.shared::cta.b64 p, [%1], %2;\n\t"
        "selp.b32 %0, 1, 0, p;\n\t}"
        : "=r"(done) : "r"(mbar), "r"(parity) : "memory");
    if (!done) {
        asm volatile(
            "{\n\t.reg .pred P1;\n\t"
            "WAIT_LOOP_%=:\n\t"
            "mbarrier.try_wait.parity.acquire.cta.shared::cta.b64 P1, [%0], %1, 0x989680;\n\t"
            "@P1 bra.uni WAIT_DONE_%=;\n\t"
            "bra.uni WAIT_LOOP_%=;\n\t"
            "WAIT_DONE_%=:\n\t}"
            :: "r"(mbar), "r"(parity) : "memory");
    }
}
static __device__ __forceinline__ void st_async_f32(uint32_t data_l, uint32_t mbar_l,
                                                    uint32_t rank, float v) {
    uint32_t rd, rm;
    asm volatile("mapa.shared::cluster.u32 %0, %1, %2;" : "=r"(rd) : "r"(data_l), "r"(rank));
    asm volatile("mapa.shared::cluster.u32 %0, %1, %2;" : "=r"(rm) : "r"(mbar_l), "r"(rank));
    asm volatile("st.async.shared::cluster.mbarrier::complete_tx::bytes.b32 [%0], %1, [%2];"
                 :: "r"(rd), "r"(__float_as_uint(v)), "r"(rm) : "memory");
}

// -------- warp-level bf16 MMA (sm_80+ PTX; legal under compute_103) --------
#define MMA_BF16(c, a, b) \
    asm volatile("mma.sync.aligned.m16n8k16.row.col.f32.bf16.bf16.f32 " \
        "{%0,%1,%2,%3}, {%4,%5,%6,%7}, {%8,%9}, {%0,%1,%2,%3};" \
        : "+f"((c)[0]), "+f"((c)[1]), "+f"((c)[2]), "+f"((c)[3]) \
        : "r"((a)[0]), "r"((a)[1]), "r"((a)[2]), "r"((a)[3]), \
          "r"((b)[0]), "r"((b)[1]))

// =====================================================================
// init: zero out[:,0,:], zero A pad rows (m >= 2016)
// =====================================================================
__global__ void init_kernel(float* __restrict__ out) {
    int gt = blockIdx.x * blockDim.x + threadIdx.x;
    if (gt < 32 * H_) {
        g_Ahi[2016 * H_ + gt] = __float2bfloat16(0.f);
        g_Alo[2016 * H_ + gt] = __float2bfloat16(0.f);
    }
    const int total = B_ * (V_ / 4);
    for (int i = gt; i < total; i += gridDim.x * blockDim.x) {
        int b  = i / (V_ / 4);
        int v4 = i - b * (V_ / 4);
        ((float4*)(out + (size_t)b * T_ * V_))[v4] = make_float4(0.f, 0.f, 0.f, 0.f);
    }
}

// =====================================================================
// bconv: split fc_W fp32 -> bf16 hi/lo (hi = bf16(x), lo = bf16(x - hi))
// =====================================================================
__global__ __launch_bounds__(256)
void bconv_kernel(const float* __restrict__ W) {
    int i = blockIdx.x * blockDim.x + threadIdx.x;   // float4 index
    if (i >= V_ * H_ / 4) return;
    float4 v = ((const float4*)W)[i];
    __nv_bfloat16 h0 = __float2bfloat16(v.x), h1 = __float2bfloat16(v.y);
    __nv_bfloat16 h2 = __float2bfloat16(v.z), h3 = __float2bfloat16(v.w);
    __nv_bfloat16 l0 = __float2bfloat16(v.x - __bfloat162float(h0));
    __nv_bfloat16 l1 = __float2bfloat16(v.y - __bfloat162float(h1));
    __nv_bfloat16 l2 = __float2bfloat16(v.z - __bfloat162float(h2));
    __nv_bfloat16 l3 = __float2bfloat16(v.w - __bfloat162float(h3));
    ((__nv_bfloat162*)g_Bhi)[i * 2]     = __nv_bfloat162(h0, h1);
    ((__nv_bfloat162*)g_Bhi)[i * 2 + 1] = __nv_bfloat162(h2, h3);
    ((__nv_bfloat162*)g_Blo)[i * 2]     = __nv_bfloat162(l0, l1);
    ((__nv_bfloat162*)g_Blo)[i * 2 + 1] = __nv_bfloat162(l2, l3);
}

// =====================================================================
// Xih precompute GEMM (unchanged)
// =====================================================================
template <int MODE>
__global__ __launch_bounds__(256)
void xih_kernel(const float* __restrict__ Amat, const int* __restrict__ idx,
                const float* __restrict__ Bmat, const float* __restrict__ bias) {
    const int KD = 128;
    __shared__ __align__(16) float As[16][132];
    __shared__ __align__(16) float Bs[16][132];

    const int tid = threadIdx.x;
    const int tx = tid & 15;
    const int ty = tid >> 4;
    const int n0 = blockIdx.x * 128;
    const int m0 = blockIdx.y * 128;

    const float* aP[2];
    const float* bP[2];
    int kq[2], rw[2];
#pragma unroll
    for (int l = 0; l < 2; l++) {
        int id = tid + l * 256;
        int r  = id >> 2;
        kq[l]  = (id & 3) * 4;
        rw[l]  = r;
        int rg = m0 + r;
        int tt = rg >> 5, bb = rg & 31;
        if (MODE == 1 && tt > 62) tt = 62;
        aP[l] = Amat + (size_t)idx[bb * 64 + tt] * KD;
        bP[l] = Bmat + (size_t)(n0 + r) * KD;
    }

    unsigned long long acc[8][4];
#pragma unroll
    for (int i = 0; i < 8; i++)
#pragma unroll
        for (int j = 0; j < 4; j++) acc[i][j] = 0ull;

    float4 aR[2], bR[2];
#pragma unroll
    for (int l = 0; l < 2; l++) {
        aR[l] = *(const float4*)(aP[l] + kq[l]);
        bR[l] = *(const float4*)(bP[l] + kq[l]);
    }

    const int KT = KD / 16;
    for (int kt = 0; kt < KT; kt++) {
#pragma unroll
        for (int l = 0; l < 2; l++) {
            As[kq[l] + 0][rw[l]] = aR[l].x;  As[kq[l] + 1][rw[l]] = aR[l].y;
            As[kq[l] + 2][rw[l]] = aR[l].z;  As[kq[l] + 3][rw[l]] = aR[l].w;
            Bs[kq[l] + 0][rw[l]] = bR[l].x;  Bs[kq[l] + 1][rw[l]] = bR[l].y;
            Bs[kq[l] + 2][rw[l]] = bR[l].z;  Bs[kq[l] + 3][rw[l]] = bR[l].w;
        }
        __syncthreads();
        if (kt + 1 < KT) {
            int ko = (kt + 1) * 16;
#pragma unroll
            for (int l = 0; l < 2; l++) {
                aR[l] = *(const float4*)(aP[l] + ko + kq[l]);
                bR[l] = *(const float4*)(bP[l] + ko + kq[l]);
            }
        }
#pragma unroll
        for (int k = 0; k < 16; k++) {
            float4 a0 = *(const float4*)&As[k][ty * 8];
            float4 a1 = *(const float4*)&As[k][ty * 8 + 4];
            ulonglong2 b01 = *(const ulonglong2*)&Bs[k][tx * 8];
            ulonglong2 b23 = *(const ulonglong2*)&Bs[k][tx * 8 + 4];
            unsigned long long bp[4] = {b01.x, b01.y, b23.x, b23.y};
            float am[8] = {a0.x, a0.y, a0.z, a0.w, a1.x, a1.y, a1.z, a1.w};
#pragma unroll
            for (int mi = 0; mi < 8; mi++) {
                unsigned long long ad = dup2(am[mi]);
#pragma unroll
                for (int np = 0; np < 4; np++)
                    acc[mi][np] = ffma2(ad, bp[np], acc[mi][np]);
            }
        }
        __syncthreads();
    }

    float* cbase = (MODE == 0) ? g_Xenc : g_Xdec;
#pragma unroll
    for (int mi = 0; mi < 8; mi++) {
        int rg = m0 + ty * 8 + mi;
        float* cptr = cbase + (size_t)rg * FOURH;
#pragma unroll
        for (int np = 0; np < 4; np++) {
            int n = n0 + tx * 8 + np * 2;
            float2 v = unpk(acc[mi][np]);
            float2 o; o.x = v.x + bias[n]; o.y = v.y + bias[n + 1];
            *(float2*)(cptr + n) = o;
        }
    }
}

// =====================================================================
// Persistent cluster LSTM (proven design; emits bf16 hi/lo FC A-rows)
// =====================================================================
__global__ __launch_bounds__(256) __cluster_dims__(CSIZE, 1, 1)
void lstm_kernel(const float* __restrict__ WhhE, const float* __restrict__ WhhD) {
    __shared__ __align__(16) float hSb[2][2][H_];
    __shared__ __align__(16) float gbuf[128][2][2];
    __shared__ __align__(8) unsigned long long mbar[2];

    const int tid  = threadIdx.x;
    const uint32_t rank = ctarank();
    const int cid  = blockIdx.x >> 3;
    const int r    = tid & 127;
    const int kh   = tid >> 7;
    const int g    = r >> 5;
    const int ul   = r & 31;
    const int grow = g * 256 + (int)rank * 32 + ul;
    const int b0   = cid * 2;

    const uint32_t hS_u32 = smem_u32(&hSb[0][0][0]);
    const uint32_t mb_u32 = smem_u32(&mbar[0]);

    ((float4*)&hSb[0][0][0])[tid] = make_float4(0.f, 0.f, 0.f, 0.f);
    if (tid == 0) { mbar_init(mb_u32, 1); mbar_init(mb_u32 + 8, 1); }
    cluster_sync();

    float c = 0.f;
    int ph[2] = {0, 0};
    int stepIdx = 0;

    unsigned long long wreg[64];

    for (int phase = 0; phase < 2; phase++) {
        {
            const float* wp = (phase ? WhhD : WhhE) + (size_t)grow * H_ + kh * 128;
#pragma unroll
            for (int i = 0; i < 64; i++)
                wreg[i] = *(const unsigned long long*)(wp + 2 * i);
        }

        const int nsteps = phase ? 63 : 64;
        const float* X = phase ? g_Xdec : g_Xenc;

        for (int s = 0; s < nsteps; s++) {
            const int p = stepIdx & 1;

            if (tid == 0) mbar_expect_tx(mb_u32 + 8u * (unsigned)(p ^ 1), STEP_TX_BYTES);

            float x0 = 0.f, x1 = 0.f;
            if (kh == 0) {
                size_t xr = (size_t)((s << 5) + b0) * FOURH + grow;
                x0 = X[xr];
                x1 = X[xr + FOURH];
            }

            if (stepIdx > 0) {
                mbar_wait_parity(mb_u32 + 8u * (unsigned)p, (uint32_t)ph[p]);
                ph[p] ^= 1;
            }

            unsigned long long acc0 = 0ull, acc1 = 0ull;
            const ulonglong2* h0 = (const ulonglong2*)&hSb[p][0][kh * 128];
            const ulonglong2* h1 = (const ulonglong2*)&hSb[p][1][kh * 128];
#pragma unroll
            for (int i = 0; i < 32; i++) {
                ulonglong2 ha = h0[i];
                ulonglong2 hb = h1[i];
                acc0 = ffma2(wreg[2 * i],     ha.x, acc0);
                acc0 = ffma2(wreg[2 * i + 1], ha.y, acc0);
                acc1 = ffma2(wreg[2 * i],     hb.x, acc1);
                acc1 = ffma2(wreg[2 * i + 1], hb.y, acc1);
            }
            float2 v0 = unpk(acc0), v1 = unpk(acc1);
            *(float2*)&gbuf[r][kh][0] =
                make_float2(v0.x + v0.y + x0, v1.x + v1.y + x1);
            __syncthreads();

            if (tid < 64) {
                int uu = tid & 31;
                int bb = tid >> 5;
                float ig = gbuf[0 * 32 + uu][0][bb] + gbuf[0 * 32 + uu][1][bb];
                float fg = gbuf[1 * 32 + uu][0][bb] + gbuf[1 * 32 + uu][1][bb];
                float gg = gbuf[2 * 32 + uu][0][bb] + gbuf[2 * 32 + uu][1][bb];
                float og = gbuf[3 * 32 + uu][0][bb] + gbuf[3 * 32 + uu][1][bb];
                c = fsigmoid(fg) * c + fsigmoid(ig) * ftanh(gg);
                float hv = fsigmoid(og) * ftanh(c);

                int ug = (int)rank * 32 + uu;
                uint32_t doff = hS_u32 +
                    (uint32_t)(((p ^ 1) * 2 + bb) * H_ + ug) * 4u;
                uint32_t moff = mb_u32 + 8u * (unsigned)(p ^ 1);
#pragma unroll
                for (int rr = 0; rr < CSIZE; rr++)
                    st_async_f32(doff, moff, (uint32_t)rr, hv);

                if (phase) {
                    int m = (s << 5) + b0 + bb;
                    __nv_bfloat16 hb16 = __float2bfloat16(hv);
                    g_Ahi[(size_t)m * H_ + ug] = hb16;
                    g_Alo[(size_t)m * H_ + ug] =
                        __float2bfloat16(hv - __bfloat162float(hb16));
                }
            }
            stepIdx++;
        }
    }
    cluster_sync();
}

// =====================================================================
// FC via warp-level bf16 split mma.sync.
// CTA 256 thr = 8 warps (2M x 4N); tile M=128, N=128, K=256; warp tile
// 64x32 (4x4 m16n8k16 fragments). D = AhiBhi + AhiBlo + AloBhi (fp32
// acc). SMEM stage = k16 tile in k-pair-major layout [kp(8)][row(128)]
// (uint32 = 2 bf16), row-stride 136 -> fragment LDS bank-conflict-free.
// Double-buffered, one __syncthreads per stage.
// =====================================================================
__global__ __launch_bounds__(256, 1)
void fc_mma_kernel(const float* __restrict__ bias, float* __restrict__ out) {
    __shared__ uint32_t As[2][2][8][136];   // [stage][hi/lo][kp][row]
    __shared__ uint32_t Bs[2][2][8][136];

    const int tid  = threadIdx.x;
    const int lane = tid & 31;
    const int w    = tid >> 5;
    const int wm   = w >> 2;          // 0..1
    const int wn   = w & 3;           // 0..3
    const int gq   = lane >> 2;       // groupID 0..7
    const int kp4  = lane & 3;        // k-pair-in-group 0..3
    const int n0 = blockIdx.x * 128;
    const int m0 = blockIdx.y * 128;

    // loader task: row = tid&127, hl = tid>>7; 32B (one k16 tile row)
    const int lrow = tid & 127, lhl = tid >> 7;
    const __nv_bfloat16* agp = (lhl ? g_Alo : g_Ahi) + (size_t)(m0 + lrow) * H_;
    const __nv_bfloat16* bgp = (lhl ? g_Blo : g_Bhi) + (size_t)(n0 + lrow) * H_;

    float acc[4][4][4];
#pragma unroll
    for (int mt = 0; mt < 4; mt++)
#pragma unroll
        for (int nt = 0; nt < 4; nt++)
#pragma unroll
            for (int j = 0; j < 4; j++) acc[mt][nt][j] = 0.f;

    uint4 aR0 = *(const uint4*)(agp),     aR1 = *(const uint4*)(agp + 8);
    uint4 bR0 = *(const uint4*)(bgp),     bR1 = *(const uint4*)(bgp + 8);

#pragma unroll 1
    for (int kt = 0; kt < 16; kt++) {
        const int st = kt & 1;
        // STS: scatter the 8 k-pairs of this row into [kp][row]
        {
            uint32_t* ad = &As[st][lhl][0][lrow];
            ad[0 * 136] = aR0.x; ad[1 * 136] = aR0.y;
            ad[2 * 136] = aR0.z; ad[3 * 136] = aR0.w;
            ad[4 * 136] = aR1.x; ad[5 * 136] = aR1.y;
            ad[6 * 136] = aR1.z; ad[7 * 136] = aR1.w;
            uint32_t* bd = &Bs[st][lhl][0][lrow];
            bd[0 * 136] = bR0.x; bd[1 * 136] = bR0.y;
            bd[2 * 136] = bR0.z; bd[3 * 136] = bR0.w;
            bd[4 * 136] = bR1.x; bd[5 * 136] = bR1.y;
            bd[6 * 136] = bR1.z; bd[7 * 136] = bR1.w;
        }
        // prefetch next k-tile (independent of SMEM)
        if (kt < 15) {
            const __nv_bfloat16* ap2 = agp + (kt + 1) * 16;
            const __nv_bfloat16* bp2 = bgp + (kt + 1) * 16;
            aR0 = *(const uint4*)(ap2);  aR1 = *(const uint4*)(ap2 + 8);
            bR0 = *(const uint4*)(bp2);  bR1 = *(const uint4*)(bp2 + 8);
        }
        __syncthreads();

        // fragment loads (conflict-free: bank = (8*kp + row) % 32)
        const uint32_t* Ah = &As[st][0][0][0];
        const uint32_t* Al = &As[st][1][0][0];
        const uint32_t* Bh = &Bs[st][0][0][0];
        const uint32_t* Bl = &Bs[st][1][0][0];

        uint32_t ahi[4][4], alo[4][4], bhi[4][2], blo[4][2];
#pragma unroll
        for (int mt = 0; mt < 4; mt++) {
            int r0 = wm * 64 + mt * 16 + gq;
            ahi[mt][0] = Ah[kp4 * 136 + r0];
            ahi[mt][1] = Ah[kp4 * 136 + r0 + 8];
            ahi[mt][2] = Ah[(4 + kp4) * 136 + r0];
            ahi[mt][3] = Ah[(4 + kp4) * 136 + r0 + 8];
            alo[mt][0] = Al[kp4 * 136 + r0];
            alo[mt][1] = Al[kp4 * 136 + r0 + 8];
            alo[mt][2] = Al[(4 + kp4) * 136 + r0];
            alo[mt][3] = Al[(4 + kp4) * 136 + r0 + 8];
        }
#pragma unroll
        for (int nt = 0; nt < 4; nt++) {
            int nn = wn * 32 + nt * 8 + gq;
            bhi[nt][0] = Bh[kp4 * 136 + nn];
            bhi[nt][1] = Bh[(4 + kp4) * 136 + nn];
            blo[nt][0] = Bl[kp4 * 136 + nn];
            blo[nt][1] = Bl[(4 + kp4) * 136 + nn];
        }

#pragma unroll
        for (int mt = 0; mt < 4; mt++)
#pragma unroll
            for (int nt = 0; nt < 4; nt++)
                MMA_BF16(acc[mt][nt], ahi[mt], bhi[nt]);
#pragma unroll
        for (int mt = 0; mt < 4; mt++)
#pragma unroll
            for (int nt = 0; nt < 4; nt++)
                MMA_BF16(acc[mt][nt], ahi[mt], blo[nt]);
#pragma unroll
        for (int mt = 0; mt < 4; mt++)
#pragma unroll
            for (int nt = 0; nt < 4; nt++)
                MMA_BF16(acc[mt][nt], alo[mt], bhi[nt]);

        __syncthreads();
    }

    // epilogue: bias + scatter out[b][t+1][v]; C frag rows g, g+8
    float2 bv[4];
#pragma unroll
    for (int nt = 0; nt < 4; nt++)
        bv[nt] = *(const float2*)(bias + n0 + wn * 32 + nt * 8 + kp4 * 2);

#pragma unroll
    for (int mt = 0; mt < 4; mt++) {
        int r1 = m0 + wm * 64 + mt * 16 + gq;
        int r2 = r1 + 8;
        float* cp1 = nullptr;
        float* cp2 = nullptr;
        if (r1 < 2016)
            cp1 = out + (size_t)(r1 & 31) * ((size_t)T_ * V_)
                  + (size_t)((r1 >> 5) + 1) * V_;
        if (r2 < 2016)
            cp2 = out + (size_t)(r2 & 31) * ((size_t)T_ * V_)
                  + (size_t)((r2 >> 5) + 1) * V_;
#pragma unroll
        for (int nt = 0; nt < 4; nt++) {
            int n = n0 + wn * 32 + nt * 8 + kp4 * 2;
            if (cp1) {
                float2 o1 = make_float2(acc[mt][nt][0] + bv[nt].x,
                                        acc[mt][nt][1] + bv[nt].y);
                *(float2*)(cp1 + n) = o1;
            }
            if (cp2) {
                float2 o2 = make_float2(acc[mt][nt][2] + bv[nt].x,
                                        acc[mt][nt][3] + bv[nt].y);
                *(float2*)(cp2 + n) = o2;
            }
        }
    }
}

// =====================================================================
extern "C" void kernel_launch(void* const* d_in, const int* in_sizes, int n_in,
                              void* d_out, int out_size) {
    const int*   src  = (const int*)d_in[0];
    const int*   trg  = (const int*)d_in[1];
    const float* eemb = (const float*)d_in[2];
    const float* eWih = (const float*)d_in[3];
    const float* eWhh = (const float*)d_in[4];
    const float* eb   = (const float*)d_in[5];
    const float* demb = (const float*)d_in[6];
    const float* dWih = (const float*)d_in[7];
    const float* dWhh = (const float*)d_in[8];
    const float* db   = (const float*)d_in[9];
    const float* fcW  = (const float*)d_in[10];
    const float* fcb  = (const float*)d_in[11];
    float* out = (float*)d_out;

    init_kernel<<<256, 256>>>(out);
    bconv_kernel<<<(V_ * H_ / 4 + 255) / 256, 256>>>(fcW);
    xih_kernel<0><<<dim3(8, 16), 256>>>(eemb, src, eWih, eb);
    xih_kernel<1><<<dim3(8, 16), 256>>>(demb, trg, dWih, db);
    lstm_kernel<<<LSTM_CTAS, 256>>>(eWhh, dWhh);
    fc_mma_kernel<<<dim3(V_ / 128, MPAD / 128), 256>>>(fcb, out);
}